// round 9
// baseline (speedup 1.0000x reference)
#include <cuda_runtime.h>
#include <cuda_fp16.h>
#include <math.h>
#include <stdint.h>
#include <string.h>

#define D_MODEL 256
#define NH 8
#define NL 4
#define NP 4
#define DHEAD 32
#define BATCH 2
#define MAX_M 40960   // >= BATCH * Lq = 39894

// Scratch (static device globals -- no allocation at runtime)
__device__ __half g_valh[(size_t)MAX_M * D_MODEL];   // value, fp16 (N,H,Lv,Dh)
__device__ float  g_off [(size_t)MAX_M * D_MODEL];   // (N,Lq,H,L,P,2)
__device__ float  g_attn[(size_t)MAX_M * (NH*NL*NP)];// logits (N,Lq,H,16)
__device__ float  g_acc [(size_t)MAX_M * D_MODEL];   // (N,Lq,H,Dh)
__device__ float  g_Wqk [384 * 256];                 // W_samp ++ W_attn
__device__ float  g_bqk [384];

// ---------------------------------------------------------------------------
// helpers
// ---------------------------------------------------------------------------
__device__ __forceinline__ uint32_t s_addr(const void* p) {
    uint32_t a;
    asm("{ .reg .u64 t; cvta.to.shared.u64 t, %1; cvt.u32.u64 %0, t; }" : "=r"(a) : "l"(p));
    return a;
}
__device__ __forceinline__ void ldsm_x4(uint32_t& r0, uint32_t& r1, uint32_t& r2, uint32_t& r3,
                                        uint32_t addr) {
    asm volatile("ldmatrix.sync.aligned.m8n8.x4.shared.b16 {%0,%1,%2,%3}, [%4];"
                 : "=r"(r0), "=r"(r1), "=r"(r2), "=r"(r3) : "r"(addr));
}
__device__ __forceinline__ void mma_f16(float* c, const uint32_t* a, const uint32_t* b) {
    asm volatile(
        "mma.sync.aligned.m16n8k16.row.col.f32.f16.f16.f32 "
        "{%0,%1,%2,%3}, {%4,%5,%6,%7}, {%8,%9}, {%0,%1,%2,%3};"
        : "+f"(c[0]), "+f"(c[1]), "+f"(c[2]), "+f"(c[3])
        : "r"(a[0]), "r"(a[1]), "r"(a[2]), "r"(a[3]), "r"(b[0]), "r"(b[1]));
}
__device__ __forceinline__ uint32_t h2bits(float x, float y) {
    const __half2 h = __float22half2_rn(make_float2(x, y));
    uint32_t u;
    memcpy(&u, &h, 4);
    return u;
}
__device__ __forceinline__ float2 bits2f2(uint32_t u) {
    __half2 h;
    memcpy(&h, &u, 4);
    return __half22float2(h);
}

// ---------------------------------------------------------------------------
// FP16 mma.sync GEMM (fp32 accum): C[M,Ncols] = A[M,256] @ W[Ncols,256]^T + b
// CTA tile 128x128, 8 warps x (64x32), m16n8k16, ldmatrix frags, dbl-buffered.
// EPI 0: row-major f32 (stride 256). EPI 1: value remap -> fp16. EPI 2: split.
// ---------------------------------------------------------------------------
#define BM 128
#define BN 128
#define BKK 32
#define PADH 8

template<int EPI>
__global__ __launch_bounds__(256)
void hgemm_nt(const float* __restrict__ A, const float* __restrict__ W,
              const float* __restrict__ bias, float* __restrict__ C0,
              float* __restrict__ C1, __half* __restrict__ CH, int M, int Lv)
{
    __shared__ alignas(16) __half As[2][BM][BKK + PADH];
    __shared__ alignas(16) __half Bs[2][BN][BKK + PADH];

    const int tid  = threadIdx.x;
    const int brow = blockIdx.x * BM;
    const int bcol = blockIdx.y * BN;
    const int K = 256;

    const int warp = tid >> 5;
    const int lane = tid & 31;
    const int wm   = (warp & 1) * 64;     // warp M offset
    const int wn   = (warp >> 1) * 32;    // warp N offset
    const int lr   = lane >> 2;           // 0..7
    const int lc   = lane & 3;            // 0..3

    const int ldRow = tid >> 1;           // 0..127
    const int ldSeg = (tid & 1) * 16;     // 0 or 16 (K elements)
    const int grA   = brow + ldRow;
    const int grW   = bcol + ldRow;

    // ldmatrix lane addressing (row within 16-row group, 8-half column segment)
    const int lmRow = lane & 15;
    const int lmSeg = (lane >> 4) * 8;

    uint32_t ua[8], uw[8];

    // prefetch tile 0 (load + convert)
    {
        float4 pa, pw;
#pragma unroll
        for (int j = 0; j < 4; j++) {
            pa = (grA < M) ? *reinterpret_cast<const float4*>(A + (size_t)grA * K + ldSeg + j * 4)
                           : make_float4(0.f, 0.f, 0.f, 0.f);
            pw = *reinterpret_cast<const float4*>(W + (size_t)grW * K + ldSeg + j * 4);
            ua[2 * j] = h2bits(pa.x, pa.y); ua[2 * j + 1] = h2bits(pa.z, pa.w);
            uw[2 * j] = h2bits(pw.x, pw.y); uw[2 * j + 1] = h2bits(pw.z, pw.w);
        }
        *reinterpret_cast<uint4*>(&As[0][ldRow][ldSeg]) = make_uint4(ua[0], ua[1], ua[2], ua[3]);
        *reinterpret_cast<uint4*>(&As[0][ldRow][ldSeg + 8]) = make_uint4(ua[4], ua[5], ua[6], ua[7]);
        *reinterpret_cast<uint4*>(&Bs[0][ldRow][ldSeg]) = make_uint4(uw[0], uw[1], uw[2], uw[3]);
        *reinterpret_cast<uint4*>(&Bs[0][ldRow][ldSeg + 8]) = make_uint4(uw[4], uw[5], uw[6], uw[7]);
    }
    __syncthreads();

    float acc[4][4][4];
#pragma unroll
    for (int mt = 0; mt < 4; mt++)
#pragma unroll
        for (int nt = 0; nt < 4; nt++)
#pragma unroll
            for (int r = 0; r < 4; r++) acc[mt][nt][r] = 0.f;

    const int nk = K / BKK;               // 8
    for (int t = 0; t < nk; t++) {
        const int cur = t & 1;
        if (t + 1 < nk) {
            const int kt = (t + 1) * BKK;
            float4 pa, pw;
#pragma unroll
            for (int j = 0; j < 4; j++) {
                pa = (grA < M) ? *reinterpret_cast<const float4*>(A + (size_t)grA * K + kt + ldSeg + j * 4)
                               : make_float4(0.f, 0.f, 0.f, 0.f);
                pw = *reinterpret_cast<const float4*>(W + (size_t)grW * K + kt + ldSeg + j * 4);
                ua[2 * j] = h2bits(pa.x, pa.y); ua[2 * j + 1] = h2bits(pa.z, pa.w);
                uw[2 * j] = h2bits(pw.x, pw.y); uw[2 * j + 1] = h2bits(pw.z, pw.w);
            }
        }

#pragma unroll
        for (int ks = 0; ks < 2; ks++) {
            const int kb = ks * 16;
            uint32_t af[4][4], bf[4][2];
#pragma unroll
            for (int mt = 0; mt < 4; mt++) {
                const uint32_t ad = s_addr(&As[cur][wm + mt * 16 + lmRow][kb + lmSeg]);
                ldsm_x4(af[mt][0], af[mt][1], af[mt][2], af[mt][3], ad);
            }
#pragma unroll
            for (int nb = 0; nb < 2; nb++) {
                const uint32_t bd = s_addr(&Bs[cur][wn + nb * 16 + lmRow][kb + lmSeg]);
                ldsm_x4(bf[2 * nb][0], bf[2 * nb + 1][0], bf[2 * nb][1], bf[2 * nb + 1][1], bd);
            }
#pragma unroll
            for (int mt = 0; mt < 4; mt++)
#pragma unroll
                for (int nt = 0; nt < 4; nt++)
                    mma_f16(acc[mt][nt], af[mt], bf[nt]);
        }

        if (t + 1 < nk) {
            const int nxt = cur ^ 1;
            *reinterpret_cast<uint4*>(&As[nxt][ldRow][ldSeg]) = make_uint4(ua[0], ua[1], ua[2], ua[3]);
            *reinterpret_cast<uint4*>(&As[nxt][ldRow][ldSeg + 8]) = make_uint4(ua[4], ua[5], ua[6], ua[7]);
            *reinterpret_cast<uint4*>(&Bs[nxt][ldRow][ldSeg]) = make_uint4(uw[0], uw[1], uw[2], uw[3]);
            *reinterpret_cast<uint4*>(&Bs[nxt][ldRow][ldSeg + 8]) = make_uint4(uw[4], uw[5], uw[6], uw[7]);
        }
        __syncthreads();
    }

    // Epilogue: mma tile rows {lr, lr+8}, cols {2*lc, 2*lc+1}
#pragma unroll
    for (int mt = 0; mt < 4; mt++) {
#pragma unroll
        for (int nt = 0; nt < 4; nt++) {
            const int c0 = bcol + wn + nt * 8 + lc * 2;
            const float b0 = __ldg(bias + c0);
            const float b1 = __ldg(bias + c0 + 1);
#pragma unroll
            for (int rr = 0; rr < 2; rr++) {
                const int r = brow + wm + mt * 16 + lr + rr * 8;
                if (r >= M) continue;
                const float v0 = acc[mt][nt][rr * 2 + 0] + b0;
                const float v1 = acc[mt][nt][rr * 2 + 1] + b1;
                if (EPI == 0) {
                    *reinterpret_cast<float2*>(C0 + (size_t)r * 256 + c0) = make_float2(v0, v1);
                } else if (EPI == 1) {
                    const int nb = r / Lv, l = r - nb * Lv;
                    const int h = c0 >> 5, dh = c0 & 31;  // c0 even -> pair stays in one head
                    __half* p = CH + ((((size_t)(nb * NH + h)) * Lv) + l) * DHEAD + dh;
                    *reinterpret_cast<__half2*>(p) = __float22half2_rn(make_float2(v0, v1));
                } else {
                    if (c0 < 256)
                        *reinterpret_cast<float2*>(C0 + (size_t)r * 256 + c0) = make_float2(v0, v1);
                    else
                        *reinterpret_cast<float2*>(C1 + (size_t)r * 128 + (c0 - 256)) = make_float2(v0, v1);
                }
            }
        }
    }
}

// ---------------------------------------------------------------------------
// Pack W_samp ++ W_attn into one 384x256 weight (shared-A GEMM merge)
// ---------------------------------------------------------------------------
__global__ void pack_qk(const float* __restrict__ Ws, const float* __restrict__ bs,
                        const float* __restrict__ Wa, const float* __restrict__ ba)
{
    const int i = blockIdx.x * 256 + threadIdx.x;
    if (i < 65536)       g_Wqk[i] = Ws[i];
    else if (i < 98304)  g_Wqk[i] = Wa[i - 65536];
    if (i < 256)         g_bqk[i] = bs[i];
    else if (i < 384)    g_bqk[i] = ba[i - 256];
}

// ---------------------------------------------------------------------------
// Sampling + softmax, two-phase.
// Phase 1: thread (u,pt) -> softmax weight + 4 corner offsets/fused weights,
//          corner order [x0y0, x0y1, x1y0, x1y1].
// Phase 2: lane = (corner[2b], channel-quad[3b]); 1 LDG.64 per point per lane
//          (4 channels); corner reduction via shfl_xor(8)+shfl_xor(16).
// ---------------------------------------------------------------------------
__global__ __launch_bounds__(256)
void msda_sample(const float* __restrict__ ref,
                 const int* __restrict__ shapes,
                 const int* __restrict__ lstart,
                 int Lq, int total)
{
    __shared__ int   s_idx[16][16][4];
    __shared__ float s_w  [16][16][4];
    __shared__ int   s_vbase[16];

    const int tid = threadIdx.x;

    // ---------------- Phase 1 ----------------
    {
        const int u  = tid >> 4;
        const int pt = tid & 15;
        const int gu = blockIdx.x * 16 + u;
        const bool act = gu < total;

        const int h  = gu & (NH - 1);
        const int mq = gu >> 3;                    // n*Lq + q

        float logit = act ? __ldg(g_attn + (size_t)gu * 16 + pt) : 0.f;
        float mx = logit;
#pragma unroll
        for (int s = 8; s > 0; s >>= 1) mx = fmaxf(mx, __shfl_xor_sync(0xffffffffu, mx, s));
        float e = __expf(logit - mx);
        float sum = e;
#pragma unroll
        for (int s = 8; s > 0; s >>= 1) sum += __shfl_xor_sync(0xffffffffu, sum, s);
        const float aw = e / sum;

        if (act) {
            const int lvl = pt >> 2;
            const int Hl = __ldg(shapes + lvl * 2 + 0);
            const int Wl = __ldg(shapes + lvl * 2 + 1);
            const int st = __ldg(lstart + lvl);

            const float rx = __ldg(ref + (size_t)mq * (NL * 2) + lvl * 2 + 0);
            const float ry = __ldg(ref + (size_t)mq * (NL * 2) + lvl * 2 + 1);
            const float ox = __ldg(g_off + (size_t)gu * 32 + 2 * pt + 0);
            const float oy = __ldg(g_off + (size_t)gu * 32 + 2 * pt + 1);

            const float x = fmaf(rx, (float)Wl, ox) - 0.5f;
            const float y = fmaf(ry, (float)Hl, oy) - 0.5f;
            const float xf = floorf(x), yf = floorf(y);
            const float lx = x - xf, ly = y - yf;
            const int x0 = (int)xf, y0 = (int)yf;
            const int x1 = x0 + 1,  y1 = y0 + 1;

            const float vx0 = (x0 >= 0 && x0 < Wl) ? 1.f : 0.f;
            const float vx1 = (x1 >= 0 && x1 < Wl) ? 1.f : 0.f;
            const float vy0 = (y0 >= 0 && y0 < Hl) ? 1.f : 0.f;
            const float vy1 = (y1 >= 0 && y1 < Hl) ? 1.f : 0.f;

            const int x0c = min(max(x0, 0), Wl - 1);
            const int x1c = min(max(x1, 0), Wl - 1);
            const int y0c = min(max(y0, 0), Hl - 1);
            const int y1c = min(max(y1, 0), Hl - 1);

            const int r0 = (st + y0c * Wl) * DHEAD;
            const int r1 = (st + y1c * Wl) * DHEAD;
            // corner order: [x0y0, x0y1, x1y0, x1y1]
            s_idx[u][pt][0] = r0 + x0c * DHEAD;
            s_idx[u][pt][1] = r1 + x0c * DHEAD;
            s_idx[u][pt][2] = r0 + x1c * DHEAD;
            s_idx[u][pt][3] = r1 + x1c * DHEAD;

            s_w[u][pt][0] = aw * (1.f - lx) * (1.f - ly) * vx0 * vy0;
            s_w[u][pt][1] = aw * (1.f - lx) * ly * vx0 * vy1;
            s_w[u][pt][2] = aw * lx * (1.f - ly) * vx1 * vy0;
            s_w[u][pt][3] = aw * lx * ly * vx1 * vy1;

            if (pt == 0) {
                const int n = mq / Lq;
                s_vbase[u] = ((n * NH + h) * Lq) * DHEAD;
            }
        }
    }
    __syncthreads();

    // ---------------- Phase 2 ----------------
    {
        const int warp   = tid >> 5;
        const int lane   = tid & 31;
        const int corner = lane >> 3;     // 0..3
        const int cq     = lane & 7;      // channel quad (4 channels)
#pragma unroll
        for (int uu = 0; uu < 2; uu++) {
            const int u  = warp * 2 + uu;
            const int gu = blockIdx.x * 16 + u;
            if (gu >= total) continue;

            const __half* bp = g_valh + s_vbase[u] + cq * 4;
            float a0 = 0.f, a1 = 0.f, a2 = 0.f, a3 = 0.f;
#pragma unroll
            for (int pt = 0; pt < 16; pt++) {
                const int   id = s_idx[u][pt][corner];
                const float w  = s_w[u][pt][corner];
                const uint2 v  = *reinterpret_cast<const uint2*>(bp + id);
                const float2 va = bits2f2(v.x);
                const float2 vb = bits2f2(v.y);
                a0 = fmaf(w, va.x, a0);
                a1 = fmaf(w, va.y, a1);
                a2 = fmaf(w, vb.x, a2);
                a3 = fmaf(w, vb.y, a3);
            }
            a0 += __shfl_xor_sync(0xffffffffu, a0, 8);
            a1 += __shfl_xor_sync(0xffffffffu, a1, 8);
            a2 += __shfl_xor_sync(0xffffffffu, a2, 8);
            a3 += __shfl_xor_sync(0xffffffffu, a3, 8);
            a0 += __shfl_xor_sync(0xffffffffu, a0, 16);
            a1 += __shfl_xor_sync(0xffffffffu, a1, 16);
            a2 += __shfl_xor_sync(0xffffffffu, a2, 16);
            a3 += __shfl_xor_sync(0xffffffffu, a3, 16);
            if (lane < 8)
                *reinterpret_cast<float4*>(g_acc + (size_t)gu * DHEAD + cq * 4)
                    = make_float4(a0, a1, a2, a3);
        }
    }
}

// ---------------------------------------------------------------------------
// Launch
// ---------------------------------------------------------------------------
extern "C" void kernel_launch(void* const* d_in, const int* in_sizes, int n_in,
                              void* d_out, int out_size)
{
    const float* query  = (const float*)d_in[0];
    const float* refp   = (const float*)d_in[1];
    const float* xin    = (const float*)d_in[2];
    const int*   shapes = (const int*)  d_in[3];
    const int*   lstart = (const int*)  d_in[4];
    const float* W_samp = (const float*)d_in[5];
    const float* b_samp = (const float*)d_in[6];
    const float* W_attn = (const float*)d_in[7];
    const float* b_attn = (const float*)d_in[8];
    const float* W_val  = (const float*)d_in[9];
    const float* b_val  = (const float*)d_in[10];
    const float* W_out  = (const float*)d_in[11];
    const float* b_out  = (const float*)d_in[12];
    float* out = (float*)d_out;

    const int Lq = in_sizes[0] / (BATCH * D_MODEL);
    const int M  = BATCH * Lq;

    void *pvh, *po, *pa, *pc, *pwqk, *pbqk;
    cudaGetSymbolAddress(&pvh, g_valh);
    cudaGetSymbolAddress(&po, g_off);
    cudaGetSymbolAddress(&pa, g_attn);
    cudaGetSymbolAddress(&pc, g_acc);
    cudaGetSymbolAddress(&pwqk, g_Wqk);
    cudaGetSymbolAddress(&pbqk, g_bqk);

    const int gx = (M + BM - 1) / BM;
    dim3 blk(256);

    // 0) pack merged qk weights
    pack_qk<<<384, blk>>>(W_samp, b_samp, W_attn, b_attn);
    // 1) value projection (+ layout remap to (N,H,Lv,Dh), fp16 out)
    hgemm_nt<1><<<dim3(gx, 2), blk>>>(xin, W_val, b_val, nullptr, nullptr, (__half*)pvh, M, Lq);
    // 2+3) merged sampling-offset + attention-logit projection (N = 384)
    hgemm_nt<2><<<dim3(gx, 3), blk>>>(query, (const float*)pwqk, (const float*)pbqk,
                                      (float*)po, (float*)pa, nullptr, M, Lq);
    // 4) softmax + deformable sampling
    {
        const int total = M * NH;
        const int nblk  = (total + 15) / 16;
        msda_sample<<<nblk, blk>>>(refp, shapes, lstart, Lq, total);
    }
    // 5) output projection
    hgemm_nt<0><<<dim3(gx, 2), blk>>>((const float*)pc, W_out, b_out, out, nullptr, nullptr, M, Lq);
}

// round 10
// speedup vs baseline: 1.1923x; 1.1923x over previous
#include <cuda_runtime.h>
#include <cuda_fp16.h>
#include <math.h>
#include <stdint.h>
#include <string.h>

#define D_MODEL 256
#define NH 8
#define NL 4
#define NP 4
#define DHEAD 32
#define BATCH 2
#define MAX_M 40960   // >= BATCH * Lq = 39894

// Scratch (static device globals -- no allocation at runtime)
__device__ __half g_valh[(size_t)MAX_M * D_MODEL];   // value, fp16 (N,H,Lv,Dh)
__device__ __half g_qh  [(size_t)MAX_M * D_MODEL];   // query, fp16
__device__ __half g_xh  [(size_t)MAX_M * D_MODEL];   // input_flatten, fp16
__device__ __half g_acch[(size_t)MAX_M * D_MODEL];   // sampled acc, fp16
__device__ float  g_off [(size_t)MAX_M * D_MODEL];   // (N,Lq,H,L,P,2)
__device__ float  g_attn[(size_t)MAX_M * (NH*NL*NP)];// logits (N,Lq,H,16)
__device__ __half g_Whv [256 * 256];                 // W_val fp16
__device__ __half g_Who [256 * 256];                 // W_out fp16
__device__ __half g_Whqk[384 * 256];                 // W_samp ++ W_attn fp16
__device__ float  g_bqk [384];

// ---------------------------------------------------------------------------
// helpers
// ---------------------------------------------------------------------------
__device__ __forceinline__ uint32_t s_addr(const void* p) {
    uint32_t a;
    asm("{ .reg .u64 t; cvta.to.shared.u64 t, %1; cvt.u32.u64 %0, t; }" : "=r"(a) : "l"(p));
    return a;
}
__device__ __forceinline__ void cp16(uint32_t dst, const void* src) {
    asm volatile("cp.async.ca.shared.global [%0], [%1], 16;" :: "r"(dst), "l"(src));
}
#define CP_COMMIT() asm volatile("cp.async.commit_group;" ::: "memory")
#define CP_WAIT(n)  asm volatile("cp.async.wait_group %0;" :: "n"(n) : "memory")

__device__ __forceinline__ void ldsm_x4(uint32_t& r0, uint32_t& r1, uint32_t& r2, uint32_t& r3,
                                        uint32_t addr) {
    asm volatile("ldmatrix.sync.aligned.m8n8.x4.shared.b16 {%0,%1,%2,%3}, [%4];"
                 : "=r"(r0), "=r"(r1), "=r"(r2), "=r"(r3) : "r"(addr));
}
__device__ __forceinline__ void mma_f16(float* c, const uint32_t* a, const uint32_t* b) {
    asm volatile(
        "mma.sync.aligned.m16n8k16.row.col.f32.f16.f16.f32 "
        "{%0,%1,%2,%3}, {%4,%5,%6,%7}, {%8,%9}, {%0,%1,%2,%3};"
        : "+f"(c[0]), "+f"(c[1]), "+f"(c[2]), "+f"(c[3])
        : "r"(a[0]), "r"(a[1]), "r"(a[2]), "r"(a[3]), "r"(b[0]), "r"(b[1]));
}
__device__ __forceinline__ uint32_t h2u(float x, float y) {
    const __half2 h = __float22half2_rn(make_float2(x, y));
    uint32_t u;
    memcpy(&u, &h, 4);
    return u;
}
__device__ __forceinline__ float2 bits2f2(uint32_t u) {
    __half2 h;
    memcpy(&h, &u, 4);
    return __half22float2(h);
}

// ---------------------------------------------------------------------------
// fp32 -> fp16 conversion (grid-strided, vectorized)
// ---------------------------------------------------------------------------
__global__ void f2h(const float* __restrict__ src, __half* __restrict__ dst, int n4)
{
    for (int i = blockIdx.x * blockDim.x + threadIdx.x; i < n4; i += gridDim.x * blockDim.x) {
        const float4 v = reinterpret_cast<const float4*>(src)[i];
        uint2 u;
        u.x = h2u(v.x, v.y);
        u.y = h2u(v.z, v.w);
        reinterpret_cast<uint2*>(dst)[i] = u;
    }
}

// Pack W_samp ++ W_attn -> fp16 merged weight + bias
__global__ void pack_qk(const float* __restrict__ Ws, const float* __restrict__ bs,
                        const float* __restrict__ Wa, const float* __restrict__ ba)
{
    const int i = blockIdx.x * 256 + threadIdx.x;   // quad index over 384*256/4
    if (i < 16384) {
        const float4 v = reinterpret_cast<const float4*>(Ws)[i];
        uint2 u; u.x = h2u(v.x, v.y); u.y = h2u(v.z, v.w);
        reinterpret_cast<uint2*>(g_Whqk)[i] = u;
    } else if (i < 24576) {
        const float4 v = reinterpret_cast<const float4*>(Wa)[i - 16384];
        uint2 u; u.x = h2u(v.x, v.y); u.y = h2u(v.z, v.w);
        reinterpret_cast<uint2*>(g_Whqk)[i] = u;
    }
    if (i < 256)      g_bqk[i] = bs[i];
    else if (i < 384) g_bqk[i] = ba[i - 256];
}

// ---------------------------------------------------------------------------
// FP16 mma.sync GEMM (fp32 accum), fp16 inputs, cp.async pipeline.
// CTA tile 128x128, 8 warps x (64x32), m16n8k16, ldmatrix frags, dbl-buffered.
// EPI 0: row-major f32. EPI 1: value remap -> fp16. EPI 2: off/attn split.
// ---------------------------------------------------------------------------
#define BM 128
#define BN 128
#define BKK 32
#define PADH 8
#define ROWH (BKK + PADH)          // 40 halves = 80 bytes, 16B-aligned

template<int EPI>
__global__ __launch_bounds__(256)
void hgemm_nt(const __half* __restrict__ A, const __half* __restrict__ W,
              const float* __restrict__ bias, float* __restrict__ C0,
              float* __restrict__ C1, __half* __restrict__ CH, int M, int Lv)
{
    __shared__ alignas(16) __half As[2][BM][ROWH];
    __shared__ alignas(16) __half Bs[2][BN][ROWH];

    const int tid  = threadIdx.x;
    const int brow = blockIdx.x * BM;
    const int bcol = blockIdx.y * BN;
    const int K = 256;

    const int warp = tid >> 5;
    const int lane = tid & 31;
    const int wm   = (warp & 1) * 64;     // warp M offset
    const int wn   = (warp >> 1) * 32;    // warp N offset
    const int lr   = lane >> 2;           // 0..7
    const int lc   = lane & 3;            // 0..3

    // cp.async loader mapping: 512 16B-chunks per matrix; thread does 2 each
    const int c0r = tid >> 2,  c0c = tid & 3;          // chunk tid
    const int c1r = 64 + c0r;                          // chunk tid+256
    const uint32_t sA0 = s_addr(&As[0][0][0]);
    const uint32_t sB0 = s_addr(&Bs[0][0][0]);
    const uint32_t bufBytes = BM * ROWH * 2;

    // ldmatrix lane addressing
    const int lmRow = lane & 15;
    const int lmSeg = (lane >> 4) * 8;

    const __half* Abase = A + (size_t)brow * K;
    const __half* Wbase = W + (size_t)bcol * K;

    // prologue: issue tile 0
    {
        cp16(sA0 + c0r * 80 + c0c * 16, Abase + (size_t)c0r * K + c0c * 8);
        cp16(sA0 + c1r * 80 + c0c * 16, Abase + (size_t)c1r * K + c0c * 8);
        cp16(sB0 + c0r * 80 + c0c * 16, Wbase + (size_t)c0r * K + c0c * 8);
        cp16(sB0 + c1r * 80 + c0c * 16, Wbase + (size_t)c1r * K + c0c * 8);
        CP_COMMIT();
    }

    float acc[4][4][4];
#pragma unroll
    for (int mt = 0; mt < 4; mt++)
#pragma unroll
        for (int nt = 0; nt < 4; nt++)
#pragma unroll
            for (int r = 0; r < 4; r++) acc[mt][nt][r] = 0.f;

#pragma unroll
    for (int t = 0; t < 8; t++) {
        const int cur = t & 1;
        if (t < 7) {
            const int kt = (t + 1) * BKK;
            const uint32_t dA = sA0 + (cur ^ 1) * bufBytes;
            const uint32_t dB = sB0 + (cur ^ 1) * bufBytes;
            cp16(dA + c0r * 80 + c0c * 16, Abase + (size_t)c0r * K + kt + c0c * 8);
            cp16(dA + c1r * 80 + c0c * 16, Abase + (size_t)c1r * K + kt + c0c * 8);
            cp16(dB + c0r * 80 + c0c * 16, Wbase + (size_t)c0r * K + kt + c0c * 8);
            cp16(dB + c1r * 80 + c0c * 16, Wbase + (size_t)c1r * K + kt + c0c * 8);
            CP_COMMIT();
            CP_WAIT(1);            // tile t resident, tile t+1 in flight
        } else {
            CP_WAIT(0);
        }
        __syncthreads();

#pragma unroll
        for (int ks = 0; ks < 2; ks++) {
            const int kb = ks * 16;
            uint32_t af[4][4], bf[4][2];
#pragma unroll
            for (int mt = 0; mt < 4; mt++) {
                const uint32_t ad = s_addr(&As[cur][wm + mt * 16 + lmRow][kb + lmSeg]);
                ldsm_x4(af[mt][0], af[mt][1], af[mt][2], af[mt][3], ad);
            }
#pragma unroll
            for (int nb = 0; nb < 2; nb++) {
                const uint32_t bd = s_addr(&Bs[cur][wn + nb * 16 + lmRow][kb + lmSeg]);
                ldsm_x4(bf[2 * nb][0], bf[2 * nb + 1][0], bf[2 * nb][1], bf[2 * nb + 1][1], bd);
            }
#pragma unroll
            for (int mt = 0; mt < 4; mt++)
#pragma unroll
                for (int nt = 0; nt < 4; nt++)
                    mma_f16(acc[mt][nt], af[mt], bf[nt]);
        }
        __syncthreads();
    }

    // Epilogue: mma tile rows {lr, lr+8}, cols {2*lc, 2*lc+1}
#pragma unroll
    for (int mt = 0; mt < 4; mt++) {
#pragma unroll
        for (int nt = 0; nt < 4; nt++) {
            const int c0 = bcol + wn + nt * 8 + lc * 2;
            const float b0 = __ldg(bias + c0);
            const float b1 = __ldg(bias + c0 + 1);
#pragma unroll
            for (int rr = 0; rr < 2; rr++) {
                const int r = brow + wm + mt * 16 + lr + rr * 8;
                if (r >= M) continue;
                const float v0 = acc[mt][nt][rr * 2 + 0] + b0;
                const float v1 = acc[mt][nt][rr * 2 + 1] + b1;
                if (EPI == 0) {
                    *reinterpret_cast<float2*>(C0 + (size_t)r * 256 + c0) = make_float2(v0, v1);
                } else if (EPI == 1) {
                    const int nb2 = r / Lv, l = r - nb2 * Lv;
                    const int h = c0 >> 5, dh = c0 & 31;
                    __half* p = CH + ((((size_t)(nb2 * NH + h)) * Lv) + l) * DHEAD + dh;
                    *reinterpret_cast<__half2*>(p) = __float22half2_rn(make_float2(v0, v1));
                } else {
                    if (c0 < 256)
                        *reinterpret_cast<float2*>(C0 + (size_t)r * 256 + c0) = make_float2(v0, v1);
                    else
                        *reinterpret_cast<float2*>(C1 + (size_t)r * 128 + (c0 - 256)) = make_float2(v0, v1);
                }
            }
        }
    }
}

// ---------------------------------------------------------------------------
// Sampling + softmax, two-phase (round-9 layout, fp16 acc output)
// ---------------------------------------------------------------------------
__global__ __launch_bounds__(256)
void msda_sample(const float* __restrict__ ref,
                 const int* __restrict__ shapes,
                 const int* __restrict__ lstart,
                 int Lq, int total)
{
    __shared__ int   s_idx[16][16][4];
    __shared__ float s_w  [16][16][4];
    __shared__ int   s_vbase[16];

    const int tid = threadIdx.x;

    // ---------------- Phase 1 ----------------
    {
        const int u  = tid >> 4;
        const int pt = tid & 15;
        const int gu = blockIdx.x * 16 + u;
        const bool act = gu < total;

        const int h  = gu & (NH - 1);
        const int mq = gu >> 3;                    // n*Lq + q

        float logit = act ? __ldg(g_attn + (size_t)gu * 16 + pt) : 0.f;
        float mx = logit;
#pragma unroll
        for (int s = 8; s > 0; s >>= 1) mx = fmaxf(mx, __shfl_xor_sync(0xffffffffu, mx, s));
        float e = __expf(logit - mx);
        float sum = e;
#pragma unroll
        for (int s = 8; s > 0; s >>= 1) sum += __shfl_xor_sync(0xffffffffu, sum, s);
        const float aw = e / sum;

        if (act) {
            const int lvl = pt >> 2;
            const int Hl = __ldg(shapes + lvl * 2 + 0);
            const int Wl = __ldg(shapes + lvl * 2 + 1);
            const int st = __ldg(lstart + lvl);

            const float rx = __ldg(ref + (size_t)mq * (NL * 2) + lvl * 2 + 0);
            const float ry = __ldg(ref + (size_t)mq * (NL * 2) + lvl * 2 + 1);
            const float ox = __ldg(g_off + (size_t)gu * 32 + 2 * pt + 0);
            const float oy = __ldg(g_off + (size_t)gu * 32 + 2 * pt + 1);

            const float x = fmaf(rx, (float)Wl, ox) - 0.5f;
            const float y = fmaf(ry, (float)Hl, oy) - 0.5f;
            const float xf = floorf(x), yf = floorf(y);
            const float lx = x - xf, ly = y - yf;
            const int x0 = (int)xf, y0 = (int)yf;
            const int x1 = x0 + 1,  y1 = y0 + 1;

            const float vx0 = (x0 >= 0 && x0 < Wl) ? 1.f : 0.f;
            const float vx1 = (x1 >= 0 && x1 < Wl) ? 1.f : 0.f;
            const float vy0 = (y0 >= 0 && y0 < Hl) ? 1.f : 0.f;
            const float vy1 = (y1 >= 0 && y1 < Hl) ? 1.f : 0.f;

            const int x0c = min(max(x0, 0), Wl - 1);
            const int x1c = min(max(x1, 0), Wl - 1);
            const int y0c = min(max(y0, 0), Hl - 1);
            const int y1c = min(max(y1, 0), Hl - 1);

            const int r0 = (st + y0c * Wl) * DHEAD;
            const int r1 = (st + y1c * Wl) * DHEAD;
            // corner order: [x0y0, x0y1, x1y0, x1y1]
            s_idx[u][pt][0] = r0 + x0c * DHEAD;
            s_idx[u][pt][1] = r1 + x0c * DHEAD;
            s_idx[u][pt][2] = r0 + x1c * DHEAD;
            s_idx[u][pt][3] = r1 + x1c * DHEAD;

            s_w[u][pt][0] = aw * (1.f - lx) * (1.f - ly) * vx0 * vy0;
            s_w[u][pt][1] = aw * (1.f - lx) * ly * vx0 * vy1;
            s_w[u][pt][2] = aw * lx * (1.f - ly) * vx1 * vy0;
            s_w[u][pt][3] = aw * lx * ly * vx1 * vy1;

            if (pt == 0) {
                const int n = mq / Lq;
                s_vbase[u] = ((n * NH + h) * Lq) * DHEAD;
            }
        }
    }
    __syncthreads();

    // ---------------- Phase 2 ----------------
    {
        const int warp   = tid >> 5;
        const int lane   = tid & 31;
        const int corner = lane >> 3;     // 0..3
        const int cq     = lane & 7;      // channel quad (4 channels)
#pragma unroll
        for (int uu = 0; uu < 2; uu++) {
            const int u  = warp * 2 + uu;
            const int gu = blockIdx.x * 16 + u;
            if (gu >= total) continue;

            const __half* bp = g_valh + s_vbase[u] + cq * 4;
            float a0 = 0.f, a1 = 0.f, a2 = 0.f, a3 = 0.f;
#pragma unroll
            for (int pt = 0; pt < 16; pt++) {
                const int   id = s_idx[u][pt][corner];
                const float w  = s_w[u][pt][corner];
                const uint2 v  = *reinterpret_cast<const uint2*>(bp + id);
                const float2 va = bits2f2(v.x);
                const float2 vb = bits2f2(v.y);
                a0 = fmaf(w, va.x, a0);
                a1 = fmaf(w, va.y, a1);
                a2 = fmaf(w, vb.x, a2);
                a3 = fmaf(w, vb.y, a3);
            }
            a0 += __shfl_xor_sync(0xffffffffu, a0, 8);
            a1 += __shfl_xor_sync(0xffffffffu, a1, 8);
            a2 += __shfl_xor_sync(0xffffffffu, a2, 8);
            a3 += __shfl_xor_sync(0xffffffffu, a3, 8);
            a0 += __shfl_xor_sync(0xffffffffu, a0, 16);
            a1 += __shfl_xor_sync(0xffffffffu, a1, 16);
            a2 += __shfl_xor_sync(0xffffffffu, a2, 16);
            a3 += __shfl_xor_sync(0xffffffffu, a3, 16);
            if (lane < 8) {
                uint2 u2;
                u2.x = h2u(a0, a1);
                u2.y = h2u(a2, a3);
                *reinterpret_cast<uint2*>(g_acch + (size_t)gu * DHEAD + cq * 4) = u2;
            }
        }
    }
}

// ---------------------------------------------------------------------------
// Launch
// ---------------------------------------------------------------------------
extern "C" void kernel_launch(void* const* d_in, const int* in_sizes, int n_in,
                              void* d_out, int out_size)
{
    const float* query  = (const float*)d_in[0];
    const float* refp   = (const float*)d_in[1];
    const float* xin    = (const float*)d_in[2];
    const int*   shapes = (const int*)  d_in[3];
    const int*   lstart = (const int*)  d_in[4];
    const float* W_samp = (const float*)d_in[5];
    const float* b_samp = (const float*)d_in[6];
    const float* W_attn = (const float*)d_in[7];
    const float* b_attn = (const float*)d_in[8];
    const float* W_val  = (const float*)d_in[9];
    const float* b_val  = (const float*)d_in[10];
    const float* W_out  = (const float*)d_in[11];
    const float* b_out  = (const float*)d_in[12];
    float* out = (float*)d_out;

    const int Lq = in_sizes[0] / (BATCH * D_MODEL);
    const int M  = BATCH * Lq;

    void *pvh, *pqh, *pxh, *pacch, *po, *pa, *pwhv, *pwho, *pwhqk, *pbqk;
    cudaGetSymbolAddress(&pvh,  g_valh);
    cudaGetSymbolAddress(&pqh,  g_qh);
    cudaGetSymbolAddress(&pxh,  g_xh);
    cudaGetSymbolAddress(&pacch,g_acch);
    cudaGetSymbolAddress(&po,   g_off);
    cudaGetSymbolAddress(&pa,   g_attn);
    cudaGetSymbolAddress(&pwhv, g_Whv);
    cudaGetSymbolAddress(&pwho, g_Who);
    cudaGetSymbolAddress(&pwhqk,g_Whqk);
    cudaGetSymbolAddress(&pbqk, g_bqk);

    const int gx = (M + BM - 1) / BM;
    dim3 blk(256);
    const int n4 = M * 64;                   // M*256/4

    // 0) fp16 conversions (inputs + weights) and qk merge
    f2h<<<512, blk>>>(query, (__half*)pqh, n4);
    f2h<<<512, blk>>>(xin,   (__half*)pxh, n4);
    f2h<<<64,  blk>>>(W_val, (__half*)pwhv, 16384);
    f2h<<<64,  blk>>>(W_out, (__half*)pwho, 16384);
    pack_qk<<<96, blk>>>(W_samp, b_samp, W_attn, b_attn);
    // 1) value projection (+ layout remap to (N,H,Lv,Dh), fp16 out)
    hgemm_nt<1><<<dim3(gx, 2), blk>>>((const __half*)pxh, (const __half*)pwhv, b_val,
                                      nullptr, nullptr, (__half*)pvh, M, Lq);
    // 2+3) merged sampling-offset + attention-logit projection (N = 384)
    hgemm_nt<2><<<dim3(gx, 3), blk>>>((const __half*)pqh, (const __half*)pwhqk, (const float*)pbqk,
                                      (float*)po, (float*)pa, nullptr, M, Lq);
    // 4) softmax + deformable sampling (writes fp16 acc)
    {
        const int total = M * NH;
        const int nblk  = (total + 15) / 16;
        msda_sample<<<nblk, blk>>>(refp, shapes, lstart, Lq, total);
    }
    // 5) output projection (reads fp16 acc)
    hgemm_nt<0><<<dim3(gx, 2), blk>>>((const __half*)pacch, (const __half*)pwho, b_out,
                                      out, nullptr, nullptr, M, Lq);
}

// round 11
// speedup vs baseline: 1.3195x; 1.1067x over previous
#include <cuda_runtime.h>
#include <cuda_fp16.h>
#include <math.h>
#include <stdint.h>
#include <string.h>

#define D_MODEL 256
#define NH 8
#define NL 4
#define NP 4
#define DHEAD 32
#define BATCH 2
#define MAX_M 40960   // >= BATCH * Lq = 39894

// Scratch (static device globals -- no allocation at runtime)
__device__ __half g_valh[(size_t)MAX_M * D_MODEL];   // value, fp16 (N,H,Lv,Dh)
__device__ __half g_qh  [(size_t)MAX_M * D_MODEL];   // query, fp16
__device__ __half g_xh  [(size_t)MAX_M * D_MODEL];   // input_flatten, fp16
__device__ __half g_acch[(size_t)MAX_M * D_MODEL];   // sampled acc, fp16
__device__ float  g_off [(size_t)MAX_M * D_MODEL];   // (N,Lq,H,L,P,2)
__device__ float  g_attn[(size_t)MAX_M * (NH*NL*NP)];// logits (N,Lq,H,16)
__device__ __half g_Whv [256 * 256];                 // W_val fp16
__device__ __half g_Who [256 * 256];                 // W_out fp16
__device__ __half g_Whqk[384 * 256];                 // W_samp ++ W_attn fp16
__device__ float  g_bqk [384];

// ---------------------------------------------------------------------------
// helpers
// ---------------------------------------------------------------------------
__device__ __forceinline__ uint32_t s_addr(const void* p) {
    uint32_t a;
    asm("{ .reg .u64 t; cvta.to.shared.u64 t, %1; cvt.u32.u64 %0, t; }" : "=r"(a) : "l"(p));
    return a;
}
__device__ __forceinline__ void cp16(uint32_t dst, const void* src) {
    asm volatile("cp.async.ca.shared.global [%0], [%1], 16;" :: "r"(dst), "l"(src));
}
#define CP_COMMIT() asm volatile("cp.async.commit_group;" ::: "memory")
#define CP_WAIT(n)  asm volatile("cp.async.wait_group %0;" :: "n"(n) : "memory")

__device__ __forceinline__ void ldsm_x4(uint32_t& r0, uint32_t& r1, uint32_t& r2, uint32_t& r3,
                                        uint32_t addr) {
    asm volatile("ldmatrix.sync.aligned.m8n8.x4.shared.b16 {%0,%1,%2,%3}, [%4];"
                 : "=r"(r0), "=r"(r1), "=r"(r2), "=r"(r3) : "r"(addr));
}
__device__ __forceinline__ void mma_f16(float* c, const uint32_t* a, const uint32_t* b) {
    asm volatile(
        "mma.sync.aligned.m16n8k16.row.col.f32.f16.f16.f32 "
        "{%0,%1,%2,%3}, {%4,%5,%6,%7}, {%8,%9}, {%0,%1,%2,%3};"
        : "+f"(c[0]), "+f"(c[1]), "+f"(c[2]), "+f"(c[3])
        : "r"(a[0]), "r"(a[1]), "r"(a[2]), "r"(a[3]), "r"(b[0]), "r"(b[1]));
}
__device__ __forceinline__ uint32_t h2u(float x, float y) {
    const __half2 h = __float22half2_rn(make_float2(x, y));
    uint32_t u;
    memcpy(&u, &h, 4);
    return u;
}
__device__ __forceinline__ float2 bits2f2(uint32_t u) {
    __half2 h;
    memcpy(&h, &u, 4);
    return __half22float2(h);
}

// ---------------------------------------------------------------------------
// One-shot prep: fp32->fp16 for query/xin/W_val/W_out/W_samp/W_attn + biases
// ---------------------------------------------------------------------------
__global__ void prep(const float* __restrict__ q,  const float* __restrict__ x,
                     const float* __restrict__ Wv, const float* __restrict__ Wo,
                     const float* __restrict__ Ws, const float* __restrict__ bs,
                     const float* __restrict__ Wa, const float* __restrict__ ba,
                     int n4)
{
    const int tid0 = blockIdx.x * blockDim.x + threadIdx.x;
    if (tid0 < 256)       g_bqk[tid0] = bs[tid0];
    else if (tid0 < 384)  g_bqk[tid0] = ba[tid0 - 256];

    const int total = 2 * n4 + 3 * 16384 + 8192;
    const int stride = gridDim.x * blockDim.x;
    for (int i = tid0; i < total; i += stride) {
        int j = i;
        const float4* src;
        uint2* dst;
        if (j < n4)                        { src = (const float4*)q;  dst = (uint2*)g_qh; }
        else if ((j -= n4) < n4)           { src = (const float4*)x;  dst = (uint2*)g_xh; }
        else if ((j -= n4) < 16384)        { src = (const float4*)Wv; dst = (uint2*)g_Whv; }
        else if ((j -= 16384) < 16384)     { src = (const float4*)Wo; dst = (uint2*)g_Who; }
        else if ((j -= 16384) < 16384)     { src = (const float4*)Ws; dst = (uint2*)g_Whqk; }
        else { j -= 16384;                   src = (const float4*)Wa; dst = (uint2*)g_Whqk + 16384; }
        const float4 v = src[j];
        uint2 u;
        u.x = h2u(v.x, v.y);
        u.y = h2u(v.z, v.w);
        dst[j] = u;
    }
}

// ---------------------------------------------------------------------------
// FP16 mma.sync GEMM core (fp32 accum), cp.async double-buffered mainloop.
// ---------------------------------------------------------------------------
#define BM 128
#define BN 128
#define BKK 32
#define PADH 8
#define ROWH (BKK + PADH)          // 40 halves = 80 bytes

struct GemmCtx {
    __half As[2][BM][ROWH];
    __half Bs[2][BN][ROWH];
};

__device__ __forceinline__ void gemm_main(const __half* __restrict__ A,
                                          const __half* __restrict__ W,
                                          int brow, int bcol, GemmCtx* sm,
                                          float acc[4][4][4])
{
    const int tid  = threadIdx.x;
    const int lane = tid & 31;
    const int warp = tid >> 5;
    const int wm   = (warp & 1) * 64;
    const int wn   = (warp >> 1) * 32;
    const int K = 256;

    const int c0r = tid >> 2,  c0c = tid & 3;
    const int c1r = 64 + c0r;
    const uint32_t sA0 = s_addr(&sm->As[0][0][0]);
    const uint32_t sB0 = s_addr(&sm->Bs[0][0][0]);
    const uint32_t bufBytes = BM * ROWH * 2;

    const int lmRow = lane & 15;
    const int lmSeg = (lane >> 4) * 8;

    const __half* Abase = A + (size_t)brow * K;
    const __half* Wbase = W + (size_t)bcol * K;

    cp16(sA0 + c0r * 80 + c0c * 16, Abase + (size_t)c0r * K + c0c * 8);
    cp16(sA0 + c1r * 80 + c0c * 16, Abase + (size_t)c1r * K + c0c * 8);
    cp16(sB0 + c0r * 80 + c0c * 16, Wbase + (size_t)c0r * K + c0c * 8);
    cp16(sB0 + c1r * 80 + c0c * 16, Wbase + (size_t)c1r * K + c0c * 8);
    CP_COMMIT();

#pragma unroll
    for (int mt = 0; mt < 4; mt++)
#pragma unroll
        for (int nt = 0; nt < 4; nt++)
#pragma unroll
            for (int r = 0; r < 4; r++) acc[mt][nt][r] = 0.f;

#pragma unroll
    for (int t = 0; t < 8; t++) {
        const int cur = t & 1;
        if (t < 7) {
            const int kt = (t + 1) * BKK;
            const uint32_t dA = sA0 + (cur ^ 1) * bufBytes;
            const uint32_t dB = sB0 + (cur ^ 1) * bufBytes;
            cp16(dA + c0r * 80 + c0c * 16, Abase + (size_t)c0r * K + kt + c0c * 8);
            cp16(dA + c1r * 80 + c0c * 16, Abase + (size_t)c1r * K + kt + c0c * 8);
            cp16(dB + c0r * 80 + c0c * 16, Wbase + (size_t)c0r * K + kt + c0c * 8);
            cp16(dB + c1r * 80 + c0c * 16, Wbase + (size_t)c1r * K + kt + c0c * 8);
            CP_COMMIT();
            CP_WAIT(1);
        } else {
            CP_WAIT(0);
        }
        __syncthreads();

#pragma unroll
        for (int ks = 0; ks < 2; ks++) {
            const int kb = ks * 16;
            uint32_t af[4][4], bf[4][2];
#pragma unroll
            for (int mt = 0; mt < 4; mt++) {
                const uint32_t ad = s_addr(&sm->As[cur][wm + mt * 16 + lmRow][kb + lmSeg]);
                ldsm_x4(af[mt][0], af[mt][1], af[mt][2], af[mt][3], ad);
            }
#pragma unroll
            for (int nb = 0; nb < 2; nb++) {
                const uint32_t bd = s_addr(&sm->Bs[cur][wn + nb * 16 + lmRow][kb + lmSeg]);
                ldsm_x4(bf[2 * nb][0], bf[2 * nb + 1][0], bf[2 * nb][1], bf[2 * nb + 1][1], bd);
            }
#pragma unroll
            for (int mt = 0; mt < 4; mt++)
#pragma unroll
                for (int nt = 0; nt < 4; nt++)
                    mma_f16(acc[mt][nt], af[mt], bf[nt]);
        }
        __syncthreads();
    }
}

// Merged value + qk projection:
//   grid.y 0..1 -> value GEMM (A=g_xh, W=g_Whv), EPI: fp16 remap to (N,H,Lv,Dh)
//   grid.y 2..4 -> qk GEMM (A=g_qh, W=g_Whqk), EPI: split off(f32)/attn(f32)
__global__ __launch_bounds__(256)
void hgemm_vqk(const float* __restrict__ bval, float* __restrict__ Coff,
               float* __restrict__ Cattn, int M, int Lv)
{
    __shared__ GemmCtx sm;
    const int by = blockIdx.y;
    const bool isVal = (by < 2);
    const int bcol = (isVal ? by : by - 2) * BN;
    const int brow = blockIdx.x * BM;

    const __half* A = isVal ? g_xh : g_qh;
    const __half* W = isVal ? g_Whv : g_Whqk;
    const float* bias = isVal ? bval : g_bqk;

    float acc[4][4][4];
    gemm_main(A, W, brow, bcol, &sm, acc);

    const int tid  = threadIdx.x;
    const int lane = tid & 31;
    const int warp = tid >> 5;
    const int wm   = (warp & 1) * 64;
    const int wn   = (warp >> 1) * 32;
    const int lr   = lane >> 2;
    const int lc   = lane & 3;

#pragma unroll
    for (int mt = 0; mt < 4; mt++) {
#pragma unroll
        for (int nt = 0; nt < 4; nt++) {
            const int c0 = bcol + wn + nt * 8 + lc * 2;
            const float b0 = __ldg(bias + c0);
            const float b1 = __ldg(bias + c0 + 1);
#pragma unroll
            for (int rr = 0; rr < 2; rr++) {
                const int r = brow + wm + mt * 16 + lr + rr * 8;
                if (r >= M) continue;
                const float v0 = acc[mt][nt][rr * 2 + 0] + b0;
                const float v1 = acc[mt][nt][rr * 2 + 1] + b1;
                if (isVal) {
                    const int nb2 = r / Lv, l = r - nb2 * Lv;
                    const int h = c0 >> 5, dh = c0 & 31;
                    __half* p = g_valh + ((((size_t)(nb2 * NH + h)) * Lv) + l) * DHEAD + dh;
                    *reinterpret_cast<__half2*>(p) = __float22half2_rn(make_float2(v0, v1));
                } else if (c0 < 256) {
                    *reinterpret_cast<float2*>(Coff + (size_t)r * 256 + c0) = make_float2(v0, v1);
                } else {
                    *reinterpret_cast<float2*>(Cattn + (size_t)r * 128 + (c0 - 256)) = make_float2(v0, v1);
                }
            }
        }
    }
}

// Output projection: out[M,256] = acch @ Who^T + b_out (f32 row-major store)
__global__ __launch_bounds__(256)
void hgemm_out(const float* __restrict__ bias, float* __restrict__ C, int M)
{
    __shared__ GemmCtx sm;
    const int brow = blockIdx.x * BM;
    const int bcol = blockIdx.y * BN;

    float acc[4][4][4];
    gemm_main(g_acch, g_Who, brow, bcol, &sm, acc);

    const int tid  = threadIdx.x;
    const int lane = tid & 31;
    const int warp = tid >> 5;
    const int wm   = (warp & 1) * 64;
    const int wn   = (warp >> 1) * 32;
    const int lr   = lane >> 2;
    const int lc   = lane & 3;

#pragma unroll
    for (int mt = 0; mt < 4; mt++) {
#pragma unroll
        for (int nt = 0; nt < 4; nt++) {
            const int c0 = bcol + wn + nt * 8 + lc * 2;
            const float b0 = __ldg(bias + c0);
            const float b1 = __ldg(bias + c0 + 1);
#pragma unroll
            for (int rr = 0; rr < 2; rr++) {
                const int r = brow + wm + mt * 16 + lr + rr * 8;
                if (r >= M) continue;
                *reinterpret_cast<float2*>(C + (size_t)r * 256 + c0) =
                    make_float2(acc[mt][nt][rr * 2 + 0] + b0, acc[mt][nt][rr * 2 + 1] + b1);
            }
        }
    }
}

// ---------------------------------------------------------------------------
// Sampling + softmax, two-phase. (idx,w) interleaved as int2 -> LDS.64.
// ---------------------------------------------------------------------------
__global__ __launch_bounds__(256)
void msda_sample(const float* __restrict__ ref,
                 const int* __restrict__ shapes,
                 const int* __restrict__ lstart,
                 int Lq, int total)
{
    __shared__ int2 s_iw[16][16][4];    // (element offset, weight bits)
    __shared__ int  s_vbase[16];

    const int tid = threadIdx.x;

    // ---------------- Phase 1 ----------------
    {
        const int u  = tid >> 4;
        const int pt = tid & 15;
        const int gu = blockIdx.x * 16 + u;
        const bool act = gu < total;

        const int h  = gu & (NH - 1);
        const int mq = gu >> 3;                    // n*Lq + q

        float logit = act ? __ldg(g_attn + (size_t)gu * 16 + pt) : 0.f;
        float mx = logit;
#pragma unroll
        for (int s = 8; s > 0; s >>= 1) mx = fmaxf(mx, __shfl_xor_sync(0xffffffffu, mx, s));
        float e = __expf(logit - mx);
        float sum = e;
#pragma unroll
        for (int s = 8; s > 0; s >>= 1) sum += __shfl_xor_sync(0xffffffffu, sum, s);
        const float aw = e / sum;

        if (act) {
            const int lvl = pt >> 2;
            const int Hl = __ldg(shapes + lvl * 2 + 0);
            const int Wl = __ldg(shapes + lvl * 2 + 1);
            const int st = __ldg(lstart + lvl);

            const float rx = __ldg(ref + (size_t)mq * (NL * 2) + lvl * 2 + 0);
            const float ry = __ldg(ref + (size_t)mq * (NL * 2) + lvl * 2 + 1);
            const float ox = __ldg(g_off + (size_t)gu * 32 + 2 * pt + 0);
            const float oy = __ldg(g_off + (size_t)gu * 32 + 2 * pt + 1);

            const float x = fmaf(rx, (float)Wl, ox) - 0.5f;
            const float y = fmaf(ry, (float)Hl, oy) - 0.5f;
            const float xf = floorf(x), yf = floorf(y);
            const float lx = x - xf, ly = y - yf;
            const int x0 = (int)xf, y0 = (int)yf;
            const int x1 = x0 + 1,  y1 = y0 + 1;

            const float vx0 = (x0 >= 0 && x0 < Wl) ? 1.f : 0.f;
            const float vx1 = (x1 >= 0 && x1 < Wl) ? 1.f : 0.f;
            const float vy0 = (y0 >= 0 && y0 < Hl) ? 1.f : 0.f;
            const float vy1 = (y1 >= 0 && y1 < Hl) ? 1.f : 0.f;

            const int x0c = min(max(x0, 0), Wl - 1);
            const int x1c = min(max(x1, 0), Wl - 1);
            const int y0c = min(max(y0, 0), Hl - 1);
            const int y1c = min(max(y1, 0), Hl - 1);

            const int r0 = (st + y0c * Wl) * DHEAD;
            const int r1 = (st + y1c * Wl) * DHEAD;
            const float w00 = aw * (1.f - lx) * (1.f - ly) * vx0 * vy0;
            const float w01 = aw * (1.f - lx) * ly * vx0 * vy1;
            const float w10 = aw * lx * (1.f - ly) * vx1 * vy0;
            const float w11 = aw * lx * ly * vx1 * vy1;

            // corner order: [x0y0, x0y1, x1y0, x1y1]
            s_iw[u][pt][0] = make_int2(r0 + x0c * DHEAD, __float_as_int(w00));
            s_iw[u][pt][1] = make_int2(r1 + x0c * DHEAD, __float_as_int(w01));
            s_iw[u][pt][2] = make_int2(r0 + x1c * DHEAD, __float_as_int(w10));
            s_iw[u][pt][3] = make_int2(r1 + x1c * DHEAD, __float_as_int(w11));

            if (pt == 0) {
                const int n = mq / Lq;
                s_vbase[u] = ((n * NH + h) * Lq) * DHEAD;
            }
        }
    }
    __syncthreads();

    // ---------------- Phase 2 ----------------
    {
        const int warp   = tid >> 5;
        const int lane   = tid & 31;
        const int corner = lane >> 3;     // 0..3
        const int cq     = lane & 7;      // channel quad (4 channels)
#pragma unroll
        for (int uu = 0; uu < 2; uu++) {
            const int u  = warp * 2 + uu;
            const int gu = blockIdx.x * 16 + u;
            if (gu >= total) continue;

            const __half* bp = g_valh + s_vbase[u] + cq * 4;
            float a0 = 0.f, a1 = 0.f, a2 = 0.f, a3 = 0.f;
#pragma unroll
            for (int pt = 0; pt < 16; pt++) {
                const int2  iw = s_iw[u][pt][corner];
                const float w  = __int_as_float(iw.y);
                const uint2 v  = *reinterpret_cast<const uint2*>(bp + iw.x);
                const float2 va = bits2f2(v.x);
                const float2 vb = bits2f2(v.y);
                a0 = fmaf(w, va.x, a0);
                a1 = fmaf(w, va.y, a1);
                a2 = fmaf(w, vb.x, a2);
                a3 = fmaf(w, vb.y, a3);
            }
            a0 += __shfl_xor_sync(0xffffffffu, a0, 8);
            a1 += __shfl_xor_sync(0xffffffffu, a1, 8);
            a2 += __shfl_xor_sync(0xffffffffu, a2, 8);
            a3 += __shfl_xor_sync(0xffffffffu, a3, 8);
            a0 += __shfl_xor_sync(0xffffffffu, a0, 16);
            a1 += __shfl_xor_sync(0xffffffffu, a1, 16);
            a2 += __shfl_xor_sync(0xffffffffu, a2, 16);
            a3 += __shfl_xor_sync(0xffffffffu, a3, 16);
            if (lane < 8) {
                uint2 u2;
                u2.x = h2u(a0, a1);
                u2.y = h2u(a2, a3);
                *reinterpret_cast<uint2*>(g_acch + (size_t)gu * DHEAD + cq * 4) = u2;
            }
        }
    }
}

// ---------------------------------------------------------------------------
// Launch
// ---------------------------------------------------------------------------
extern "C" void kernel_launch(void* const* d_in, const int* in_sizes, int n_in,
                              void* d_out, int out_size)
{
    const float* query  = (const float*)d_in[0];
    const float* refp   = (const float*)d_in[1];
    const float* xin    = (const float*)d_in[2];
    const int*   shapes = (const int*)  d_in[3];
    const int*   lstart = (const int*)  d_in[4];
    const float* W_samp = (const float*)d_in[5];
    const float* b_samp = (const float*)d_in[6];
    const float* W_attn = (const float*)d_in[7];
    const float* b_attn = (const float*)d_in[8];
    const float* W_val  = (const float*)d_in[9];
    const float* b_val  = (const float*)d_in[10];
    const float* W_out  = (const float*)d_in[11];
    const float* b_out  = (const float*)d_in[12];
    float* out = (float*)d_out;

    const int Lq = in_sizes[0] / (BATCH * D_MODEL);
    const int M  = BATCH * Lq;

    void *po, *pa;
    cudaGetSymbolAddress(&po, g_off);
    cudaGetSymbolAddress(&pa, g_attn);

    const int gx = (M + BM - 1) / BM;
    dim3 blk(256);
    const int n4 = M * 64;                   // M*256/4

    // 0) one-shot fp16 conversion + weight pack
    prep<<<1024, blk>>>(query, xin, W_val, W_out, W_samp, b_samp, W_attn, b_attn, n4);
    // 1) merged value + qk projection (value -> fp16 remap; qk -> off/attn f32)
    hgemm_vqk<<<dim3(gx, 5), blk>>>(b_val, (float*)po, (float*)pa, M, Lq);
    // 2) softmax + deformable sampling (writes fp16 acc)
    {
        const int total = M * NH;
        const int nblk  = (total + 15) / 16;
        msda_sample<<<nblk, blk>>>(refp, shapes, lstart, Lq, total);
    }
    // 3) output projection
    hgemm_out<<<dim3(gx, 2), blk>>>(b_out, out, M);
}